// round 16
// baseline (speedup 1.0000x reference)
#include <cuda_runtime.h>
#include <cuda_fp16.h>
#include <cstdint>

// ---------------- scratch (device globals; no allocation allowed) ----------
__device__ float  g_r1b [1179648];  // [2][64][96][96]
__device__ float  g_r2b [1179648];  // [2][64][96][96]  query q
__device__ float  g_t48 [294912];   // [2][64][48][48]
__device__ float  g_c2r [1179648];  // [2][64][96][96]  keys
__device__ float  g_attb[165888];   // [2][9][9216]
__device__ float  g_pool[204800];
__device__ float  g_ppol[51200];
__device__ __half g_psph[18874368]; // [2][4096][48][48] psp features (half)
__device__ float  g_out5[2359296];  // [2][512][48][48]
__device__ float  g_z48 [271872];
__device__ float  g_z96 [1087488];
__device__ __half g_w5h [18874368]; // w_c5 as half, PERMUTED [512][tap*4096+cin]

__device__ __forceinline__ uint32_t smem_u32(const void* p) {
    uint32_t a;
    asm("{ .reg .u64 t; cvta.to.shared.u64 t, %1; cvt.u32.u64 %0, t; }" : "=r"(a) : "l"(p));
    return a;
}
__device__ __forceinline__ void ldsm_x4(uint32_t& r0, uint32_t& r1, uint32_t& r2,
                                        uint32_t& r3, uint32_t addr) {
    asm volatile("ldmatrix.sync.aligned.m8n8.x4.shared.b16 {%0,%1,%2,%3}, [%4];"
                 : "=r"(r0), "=r"(r1), "=r"(r2), "=r"(r3) : "r"(addr));
}
__device__ __forceinline__ void mma16n8k16(float* c, const uint32_t* a, const uint32_t* b)
{
    asm volatile(
        "mma.sync.aligned.m16n8k16.row.col.f32.f16.f16.f32 "
        "{%0,%1,%2,%3}, {%4,%5,%6,%7}, {%8,%9}, {%0,%1,%2,%3};"
        : "+f"(c[0]), "+f"(c[1]), "+f"(c[2]), "+f"(c[3])
        : "r"(a[0]), "r"(a[1]), "r"(a[2]), "r"(a[3]), "r"(b[0]), "r"(b[1]));
}

// -------- convert + permute w_c5 to half: dst[m][tap*4096+cin] = src[m][cin*9+tap]
__global__ void w2h_perm(const float* __restrict__ src, __half* __restrict__ dst)
{
    long idx = (long)blockIdx.x * 256 + threadIdx.x;
    if (idx >= 18874368L) return;
    int m   = (int)(idx / 36864);
    int kp  = (int)(idx - (long)m * 36864);
    int tap = kp >> 12;        // / 4096
    int cin = kp & 4095;
    dst[idx] = __float2half(src[(long)m * 36864 + cin * 9 + tap]);
}

// ===========================================================================
// conv5: fp16 mma.sync (f32 accum) + ldmatrix, TAP-MAJOR implicit im2col.
//   k' = tap*4096 + cin; each KC=64 chunk has a single tap -> trivial gather.
//   CTA 128x128, 16 warps (warp 32x32), double-buffered dynamic smem.
//   A smem [m][72h], B smem [n][72h]; stride 72h -> conflict-free LDSM.
// ===========================================================================
#define KC5  64
#define SAK  72
#define HBUF (2 * 128 * SAK)   // halves per (A|B) pair

__global__ void __launch_bounds__(512, 1)
c5_mma_kernel(const __half* __restrict__ Ah, const __half* __restrict__ psph,
              const float* __restrict__ bnp, float* __restrict__ Out)
{
    extern __shared__ __half smh[];
    const uint32_t smbase = smem_u32(smh);

    const int t    = threadIdx.x;
    const int wid  = t >> 5;
    const int lane = t & 31;
    const int gid  = lane >> 2;
    const int tig  = lane & 3;
    const int wm   = (wid & 3) * 32;
    const int wn   = (wid >> 2) * 32;

    const int img = blockIdx.z;
    const int bm  = blockIdx.y * 128;
    const int bp0 = blockIdx.x * 128;
    const __half* Bn = psph + (long)img * 4096 * 2304;

    const int rowA = lane & 15;
    const int colA = (lane & 16) ? 8 : 0;
    const int rowB = (lane & 7) + ((lane & 16) ? 8 : 0);
    const int colB = (lane & 8) ? 8 : 0;

    const int a_m   = t >> 3;          // 0..63
    const int a_seg = t & 7;

    int b_n[2], b_kg[2], b_py[2], b_px[2];
    #pragma unroll
    for (int u = 0; u < 2; u++) {
        int unit = u * 512 + t;
        b_n[u]  = unit & 127;
        b_kg[u] = unit >> 7;
        int pg  = bp0 + b_n[u];
        b_py[u] = pg / 48;
        b_px[u] = pg - b_py[u] * 48;
    }

    uint4 arv[2];
    __align__(16) uint16_t brv[2][8];

    auto fetchA = [&](int k0) {
        #pragma unroll
        for (int j = 0; j < 2; j++)
            arv[j] = *reinterpret_cast<const uint4*>(
                Ah + (long)(bm + a_m + j * 64) * 36864 + k0 + a_seg * 8);
    };
    // chunk ch: tap = ch>>6 (one tap per chunk), cin0 = (ch&63)*64
    auto fetchB = [&](int ch) {
        const int tap  = ch >> 6;
        const int cin0 = (ch & 63) << 6;
        const int dy   = tap / 3 - 1;
        const int dx   = tap - (tap / 3) * 3 - 1;
        #pragma unroll
        for (int u = 0; u < 2; u++) {
            int y = b_py[u] + dy;
            int x = b_px[u] + dx;
            bool valid = ((unsigned)y < 48u) && ((unsigned)x < 48u);
            const __half* bp = Bn + (long)(cin0 + b_kg[u] * 8) * 2304 + y * 48 + x;
            #pragma unroll
            for (int j = 0; j < 8; j++)
                brv[u][j] = valid ? __half_as_ushort(__ldg(bp + j * 2304))
                                  : (uint16_t)0;
        }
    };
    auto stsAB = [&](int buf) {
        __half* A = smh + buf * HBUF;
        __half* B = A + 128 * SAK;
        #pragma unroll
        for (int j = 0; j < 2; j++)
            *reinterpret_cast<uint4*>(A + (a_m + j * 64) * SAK + a_seg * 8) = arv[j];
        #pragma unroll
        for (int u = 0; u < 2; u++)
            *reinterpret_cast<uint4*>(B + b_n[u] * SAK + b_kg[u] * 8) =
                *reinterpret_cast<const uint4*>(brv[u]);
    };

    float acc[2][4][4];
    #pragma unroll
    for (int mt = 0; mt < 2; mt++)
        #pragma unroll
        for (int nt = 0; nt < 4; nt++)
            #pragma unroll
            for (int i = 0; i < 4; i++) acc[mt][nt][i] = 0.f;

    fetchA(0); fetchB(0);
    stsAB(0);
    __syncthreads();

    const int NCH = 576;  // 36864 / 64
    int buf = 0;
    for (int it = 0; it < NCH; it++) {
        if (it + 1 < NCH) { fetchA((it + 1) * KC5); fetchB(it + 1); }
        const uint32_t Abase = smbase + (uint32_t)buf * (HBUF * 2);
        const uint32_t Bbase = Abase + 128 * SAK * 2;
        #pragma unroll
        for (int s = 0; s < 4; s++) {
            uint32_t af[2][4];
            uint32_t bf[4][2];
            #pragma unroll
            for (int mt = 0; mt < 2; mt++)
                ldsm_x4(af[mt][0], af[mt][1], af[mt][2], af[mt][3],
                        Abase + (uint32_t)((wm + mt * 16 + rowA) * SAK
                                           + s * 16 + colA) * 2u);
            #pragma unroll
            for (int np = 0; np < 2; np++)
                ldsm_x4(bf[2 * np][0], bf[2 * np][1], bf[2 * np + 1][0], bf[2 * np + 1][1],
                        Bbase + (uint32_t)((wn + np * 16 + rowB) * SAK
                                           + s * 16 + colB) * 2u);
            #pragma unroll
            for (int mt = 0; mt < 2; mt++)
                #pragma unroll
                for (int nt = 0; nt < 4; nt++)
                    mma16n8k16(acc[mt][nt], af[mt], bf[nt]);
        }
        if (it + 1 < NCH) stsAB(buf ^ 1);
        __syncthreads();
        buf ^= 1;
    }

    #pragma unroll
    for (int mt = 0; mt < 2; mt++) {
        const int m0 = bm + wm + mt * 16 + gid;
        #pragma unroll
        for (int half = 0; half < 2; half++) {
            const int m = m0 + half * 8;
            const float g  = bnp[m], be = bnp[512 + m];
            const float mu = bnp[1024 + m], va = bnp[1536 + m];
            const float scale = g * rsqrtf(va + 1e-5f);
            const float shift = be - mu * scale;
            float* On = Out + ((long)img * 512 + m) * 2304 + bp0 + wn + tig * 2;
            #pragma unroll
            for (int nt = 0; nt < 4; nt++) {
                float2 v;
                v.x = fmaxf(fmaf(acc[mt][nt][half * 2],     scale, shift), 0.f);
                v.y = fmaxf(fmaf(acc[mt][nt][half * 2 + 1], scale, shift), 0.f);
                *reinterpret_cast<float2*>(On + nt * 8) = v;
            }
        }
    }
}

// ========== fp32 SGEMM, 256 threads, tile 64x128 (dilated 3x3, M=64) =======
template<int DIL>
__global__ void __launch_bounds__(256, 1)
gemm_conv64(const float* __restrict__ A, const float* __restrict__ Bin,
            const float* __restrict__ bnp, float* __restrict__ Out,
            int K, int H, int W, long inStride)
{
    __shared__ float As_[2][8][64];
    __shared__ float Bs_[2][8][128];

    const int t   = threadIdx.x;
    const int img = blockIdx.z;
    const int Npix = H * W;
    const float* Bn = Bin + (long)img * inStride;
    float*       On = Out + (long)img * 64L * Npix;
    const int bp0 = blockIdx.x * 128;
    const int tr  = t >> 4;
    const int tc  = t & 15;

    const int am  = t >> 2;
    const int ak2 = (t & 3) * 2;
    const int bk  = t >> 5;
    const int bp4 = (t & 31) * 4;

    float2 aReg;
    float  bReg[4];

    auto fetch = [&](int k0) {
        aReg = *reinterpret_cast<const float2*>(A + (long)am * K + k0 + ak2);
        int k   = k0 + bk;
        int cin = k / 9;
        int tap = k - cin * 9;
        int oy  = (tap / 3 - 1) * DIL;
        int ox  = (tap % 3 - 1) * DIL;
        const float* src = Bn + (long)cin * Npix;
        #pragma unroll
        for (int j = 0; j < 4; j++) {
            int p  = bp0 + bp4 + j;
            int py = p / W;
            int px = p - py * W;
            int y  = py + oy;
            int x  = px + ox;
            bReg[j] = ((unsigned)y < (unsigned)H && (unsigned)x < (unsigned)W)
                      ? src[y * W + x] : 0.f;
        }
    };
    auto put = [&](int buf) {
        As_[buf][ak2 + 0][am] = aReg.x;
        As_[buf][ak2 + 1][am] = aReg.y;
        #pragma unroll
        for (int j = 0; j < 4; j++) Bs_[buf][bk][bp4 + j] = bReg[j];
    };

    float acc[4][8];
    #pragma unroll
    for (int i = 0; i < 4; i++)
        #pragma unroll
        for (int j = 0; j < 8; j++) acc[i][j] = 0.f;

    fetch(0);
    put(0);
    __syncthreads();

    const int nK = K / 8;
    int buf = 0;
    for (int it = 0; it < nK; it++) {
        if (it + 1 < nK) fetch((it + 1) * 8);
        #pragma unroll
        for (int kk = 0; kk < 8; kk++) {
            float4 a0 = *reinterpret_cast<const float4*>(&As_[buf][kk][tr * 4]);
            float4 b0 = *reinterpret_cast<const float4*>(&Bs_[buf][kk][tc * 8]);
            float4 b1 = *reinterpret_cast<const float4*>(&Bs_[buf][kk][tc * 8 + 4]);
            float av[4] = {a0.x, a0.y, a0.z, a0.w};
            float bv[8] = {b0.x, b0.y, b0.z, b0.w, b1.x, b1.y, b1.z, b1.w};
            #pragma unroll
            for (int i = 0; i < 4; i++)
                #pragma unroll
                for (int j = 0; j < 8; j++)
                    acc[i][j] = fmaf(av[i], bv[j], acc[i][j]);
        }
        if (it + 1 < nK) put(buf ^ 1);
        __syncthreads();
        buf ^= 1;
    }

    #pragma unroll
    for (int i = 0; i < 4; i++) {
        int m = tr * 4 + i;
        float g  = bnp[m];
        float be = bnp[64 + m];
        float mu = bnp[128 + m];
        float va = bnp[192 + m];
        float scale = g * rsqrtf(va + 1e-5f);
        float shift = be - mu * scale;
        #pragma unroll
        for (int j = 0; j < 8; j++) {
            int p = bp0 + tc * 8 + j;
            float v = fmaxf(fmaf(acc[i][j], scale, shift), 0.f);
            On[(long)m * Npix + p] = v;
        }
    }
}

// ================= fp32 SGEMM (1x1 convs) ==================================
template<int TM, int DIL, bool BN, bool RELU, bool MCHECK, bool NCHECK>
__global__ void __launch_bounds__((TM/8)*16, 1)
gemm_conv(const float* __restrict__ A, const float* __restrict__ Bin,
          const float* __restrict__ bnp, float* __restrict__ Out,
          int M, int K, int H, int W, int Npix,
          long inStride, long outStride)
{
    constexpr int TN   = 128;
    constexpr int NT   = (TM / 8) * (TN / 8);
    constexpr int BVEC = (NT == 256) ? 4 : 8;

    __shared__ float As_[2][8][TM];
    __shared__ float Bs_[2][8][TN];

    const int tid = threadIdx.x;
    const int img = blockIdx.z;
    const float* Bn = Bin + (long)img * inStride;
    float*       On = Out + (long)img * outStride;
    const int bm  = blockIdx.y * TM;
    const int bp0 = blockIdx.x * TN;
    const int tr  = tid / 16;
    const int tc  = tid % 16;

    const int am = tid >> 1;
    const int ak = (tid & 1) * 4;
    const int bk = tid / (TN / BVEC);
    const int bp = (tid % (TN / BVEC)) * BVEC;

    float4 aReg;
    float  bReg[BVEC];

    auto fetch = [&](int k0) {
        int m = bm + am;
        if (!MCHECK || m < M)
            aReg = *reinterpret_cast<const float4*>(A + (long)m * K + k0 + ak);
        else
            aReg = make_float4(0.f, 0.f, 0.f, 0.f);
        int k = k0 + bk;
        if (DIL == 0) {
            const float* row = Bn + (long)k * Npix;
            if (!NCHECK) {
                #pragma unroll
                for (int j = 0; j < BVEC; j += 4) {
                    float4 v = *reinterpret_cast<const float4*>(row + bp0 + bp + j);
                    bReg[j] = v.x; bReg[j+1] = v.y; bReg[j+2] = v.z; bReg[j+3] = v.w;
                }
            } else {
                #pragma unroll
                for (int j = 0; j < BVEC; j++) {
                    int p = bp0 + bp + j;
                    bReg[j] = (p < Npix) ? row[p] : 0.f;
                }
            }
        } else {
            int cin = k / 9;
            int tap = k - cin * 9;
            int oy  = (tap / 3 - 1) * DIL;
            int ox  = (tap % 3 - 1) * DIL;
            const float* src = Bn + (long)cin * (H * W);
            #pragma unroll
            for (int j = 0; j < BVEC; j++) {
                int p  = bp0 + bp + j;
                int py = p / W;
                int px = p - py * W;
                int y  = py + oy;
                int x  = px + ox;
                bReg[j] = ((unsigned)y < (unsigned)H && (unsigned)x < (unsigned)W)
                          ? src[y * W + x] : 0.f;
            }
        }
    };
    auto put = [&](int buf) {
        As_[buf][ak + 0][am] = aReg.x;
        As_[buf][ak + 1][am] = aReg.y;
        As_[buf][ak + 2][am] = aReg.z;
        As_[buf][ak + 3][am] = aReg.w;
        #pragma unroll
        for (int j = 0; j < BVEC; j++) Bs_[buf][bk][bp + j] = bReg[j];
    };

    float acc[8][8];
    #pragma unroll
    for (int i = 0; i < 8; i++)
        #pragma unroll
        for (int j = 0; j < 8; j++) acc[i][j] = 0.f;

    fetch(0);
    put(0);
    __syncthreads();

    const int nK = K / 8;
    int buf = 0;
    for (int it = 0; it < nK; it++) {
        if (it + 1 < nK) fetch((it + 1) * 8);
        #pragma unroll
        for (int kk = 0; kk < 8; kk++) {
            float4 a0 = *reinterpret_cast<const float4*>(&As_[buf][kk][tr * 8]);
            float4 a1 = *reinterpret_cast<const float4*>(&As_[buf][kk][tr * 8 + 4]);
            float4 b0 = *reinterpret_cast<const float4*>(&Bs_[buf][kk][tc * 8]);
            float4 b1 = *reinterpret_cast<const float4*>(&Bs_[buf][kk][tc * 8 + 4]);
            float av[8] = {a0.x, a0.y, a0.z, a0.w, a1.x, a1.y, a1.z, a1.w};
            float bv[8] = {b0.x, b0.y, b0.z, b0.w, b1.x, b1.y, b1.z, b1.w};
            #pragma unroll
            for (int i = 0; i < 8; i++)
                #pragma unroll
                for (int j = 0; j < 8; j++)
                    acc[i][j] = fmaf(av[i], bv[j], acc[i][j]);
        }
        if (it + 1 < nK) put(buf ^ 1);
        __syncthreads();
        buf ^= 1;
    }

    #pragma unroll
    for (int i = 0; i < 8; i++) {
        int m = bm + tr * 8 + i;
        if (MCHECK && m >= M) continue;
        float scale = 1.f, shift = 0.f;
        if (BN) {
            float g  = bnp[m];
            float be = bnp[M + m];
            float mu = bnp[2 * M + m];
            float va = bnp[3 * M + m];
            scale = g * rsqrtf(va + 1e-5f);
            shift = be - mu * scale;
        }
        #pragma unroll
        for (int j = 0; j < 8; j++) {
            int p = bp0 + tc * 8 + j;
            if (NCHECK && p >= Npix) continue;
            float v = acc[i][j];
            if (BN)   v = fmaf(v, scale, shift);
            if (RELU) v = fmaxf(v, 0.f);
            On[(long)m * Npix + p] = v;
        }
    }
}

// -------- adaptive avg pool ------------------------------------------------
__global__ void pool_kernel(const float* __restrict__ x, float* __restrict__ pool)
{
    __shared__ float sm[2304];
    const int cin = blockIdx.x;
    const int n   = blockIdx.y;
    const float* src = x + ((long)n * 2048 + cin) * 2304;
    for (int i = threadIdx.x; i < 2304; i += blockDim.x) sm[i] = src[i];
    __syncthreads();
    int r = threadIdx.x;
    if (r < 50) {
        int sc, pi;
        if      (r < 1)  { sc = 0; pi = r; }
        else if (r < 5)  { sc = 1; pi = r - 1; }
        else if (r < 14) { sc = 2; pi = r - 5; }
        else             { sc = 3; pi = r - 14; }
        const int sides[4] = {1, 2, 3, 6};
        const int inoff[4] = {0, 2048, 10240, 28672};
        int side = sides[sc];
        int iy = pi / side, ix = pi % side;
        int bs = 48 / side;
        float s = 0.f;
        for (int yy = iy * bs; yy < (iy + 1) * bs; yy++)
            for (int xx = ix * bs; xx < (ix + 1) * bs; xx++)
                s += sm[yy * 48 + xx];
        pool[(long)n * 102400 + inoff[sc] + cin * (side * side) + pi] = s / (float)(bs * bs);
    }
}

struct PoolWArgs { const float* w[4]; const float* bn[4]; };

__global__ void pooled_conv_kernel(PoolWArgs args, const float* __restrict__ pool,
                                   float* __restrict__ ppool)
{
    int gw   = (blockIdx.x * blockDim.x + threadIdx.x) >> 5;
    int lane = threadIdx.x & 31;
    if (gw >= 51200) return;
    int n  = gw / 25600;
    int t  = gw % 25600;
    int pg = t / 512;
    int co = t % 512;
    int sc, pi;
    if      (pg < 1)  { sc = 0; pi = pg; }
    else if (pg < 5)  { sc = 1; pi = pg - 1; }
    else if (pg < 14) { sc = 2; pi = pg - 5; }
    else              { sc = 3; pi = pg - 14; }
    const int ssq[4]    = {1, 4, 9, 36};
    const int inoff[4]  = {0, 2048, 10240, 28672};
    const int outoff[4] = {0, 512, 2560, 7168};
    const float* w  = args.w[sc] + (long)co * 2048;
    const float* pb = pool + (long)n * 102400 + inoff[sc] + pi;
    int stride = ssq[sc];
    float acc = 0.f;
    for (int c = lane; c < 2048; c += 32)
        acc = fmaf(w[c], pb[(long)c * stride], acc);
    #pragma unroll
    for (int s = 16; s; s >>= 1) acc += __shfl_xor_sync(0xffffffffu, acc, s);
    if (lane == 0) {
        const float* bnp = args.bn[sc];
        float scale = bnp[co] * rsqrtf(bnp[1536 + co] + 1e-5f);
        float v = fmaf(acc, scale, bnp[512 + co] - bnp[1024 + co] * scale);
        ppool[(long)n * 25600 + outoff[sc] + co * stride + pi] = fmaxf(v, 0.f);
    }
}

// -------- assemble psp (HALF out, 4 px per thread) -------------------------
__global__ void psp_assemble4(const float* __restrict__ x, const float* __restrict__ ppool,
                              __half* __restrict__ psp)
{
    long q = (long)blockIdx.x * 256 + threadIdx.x;
    if (q >= 4718592L) return;          // 18874368 / 4
    long idx = q * 4;
    int p = (int)(idx % 2304);          // multiple of 4, same (n,c) for all 4
    long tt = idx / 2304;
    int c = (int)(tt % 4096);
    int n = (int)(tt / 4096);
    __half h[4];
    if (c < 2048) {
        float4 v = *reinterpret_cast<const float4*>(
            x + ((long)n * 2048 + c) * 2304 + p);
        h[0] = __float2half(v.x); h[1] = __float2half(v.y);
        h[2] = __float2half(v.z); h[3] = __float2half(v.w);
    } else {
        int sc = (c - 2048) >> 9;
        int cc = (c - 2048) & 511;
        const int sides[4]  = {1, 2, 3, 6};
        const int outoff[4] = {0, 512, 2560, 7168};
        int s = sides[sc];
        const float* f = ppool + (long)n * 25600 + outoff[sc] + cc * s * s;
        if (s == 1) {
            h[0] = h[1] = h[2] = h[3] = __float2half(f[0]);
        } else {
            int y = p / 48;
            float ratio = (float)(s - 1) / 47.0f;
            float sy = y * ratio;
            int y0 = (int)sy;
            if (y0 > s - 1) y0 = s - 1;
            int y1 = min(y0 + 1, s - 1);
            float wy = sy - y0;
            #pragma unroll
            for (int j = 0; j < 4; j++) {
                int xx = (p + j) % 48;
                float sx = xx * ratio;
                int x0 = (int)sx;
                if (x0 > s - 1) x0 = s - 1;
                int x1 = min(x0 + 1, s - 1);
                float wx = sx - x0;
                float r0 = f[y0 * s + x0] * (1.f - wx) + f[y0 * s + x1] * wx;
                float r1 = f[y1 * s + x0] * (1.f - wx) + f[y1 * s + x1] * wx;
                h[j] = __float2half(r0 * (1.f - wy) + r1 * wy);
            }
        }
    }
    uint2 packed;
    packed.x = ((uint32_t)__half_as_ushort(h[1]) << 16) | __half_as_ushort(h[0]);
    packed.y = ((uint32_t)__half_as_ushort(h[3]) << 16) | __half_as_ushort(h[2]);
    *reinterpret_cast<uint2*>(psp + idx) = packed;
}

template<bool RELU>
__global__ void ups48to96(const float* __restrict__ in, float* __restrict__ out, int total)
{
    int idx = blockIdx.x * 256 + threadIdx.x;
    if (idx >= total) return;
    int p  = idx % 9216;
    int ch = idx / 9216;
    int y = p / 96, x = p % 96;
    const float r = 47.0f / 95.0f;
    float sy = y * r, sx = x * r;
    int y0 = (int)sy, x0 = (int)sx;
    if (y0 > 47) y0 = 47;
    if (x0 > 47) x0 = 47;
    int y1 = min(y0 + 1, 47), x1 = min(x0 + 1, 47);
    float wy = sy - y0, wx = sx - x0;
    const float* f = in + (long)ch * 2304;
    float v0 = f[y0 * 48 + x0] * (1.f - wx) + f[y0 * 48 + x1] * wx;
    float v1 = f[y1 * 48 + x0] * (1.f - wx) + f[y1 * 48 + x1] * wx;
    float v  = v0 * (1.f - wy) + v1 * wy;
    if (RELU) v = fmaxf(v, 0.f);
    out[idx] = v;
}

__global__ void att_kernel(const float* __restrict__ q, const float* __restrict__ kf,
                           float* __restrict__ att)
{
    int p = blockIdx.x * 256 + threadIdx.x;
    int n = blockIdx.y;
    if (p >= 9216) return;
    int y = p / 96, x = p % 96;
    int   offs[9];
    bool  valid[9];
    #pragma unroll
    for (int k = 0; k < 9; k++) {
        int yy = y + (k / 3 - 1) * 2;
        int xx = x + (k % 3 - 1) * 2;
        valid[k] = ((unsigned)yy < 96u) && ((unsigned)xx < 96u);
        offs[k]  = valid[k] ? yy * 96 + xx : 0;
    }
    float e[9];
    #pragma unroll
    for (int k = 0; k < 9; k++) e[k] = 0.f;
    const float* qn = q  + (long)n * 64 * 9216;
    const float* kn = kf + (long)n * 64 * 9216;
    for (int c = 0; c < 64; c++) {
        float qv = qn[c * 9216 + p];
        const float* base = kn + c * 9216;
        #pragma unroll
        for (int k = 0; k < 9; k++) {
            float kv = valid[k] ? base[offs[k]] : 0.f;
            e[k] = fmaf(qv, kv, e[k]);
        }
    }
    float mx = e[0];
    #pragma unroll
    for (int k = 1; k < 9; k++) mx = fmaxf(mx, e[k]);
    float sum = 0.f;
    #pragma unroll
    for (int k = 0; k < 9; k++) { e[k] = __expf(e[k] - mx); sum += e[k]; }
    float inv = 1.f / sum;
    #pragma unroll
    for (int k = 0; k < 9; k++)
        att[(long)n * 82944 + k * 9216 + p] = e[k] * inv;
}

__global__ void final_kernel(const float* __restrict__ att, const float* __restrict__ z,
                             const float* __restrict__ bias, float* __restrict__ out)
{
    int p = blockIdx.x * 256 + threadIdx.x;
    int o = blockIdx.y;
    int n = blockIdx.z;
    if (p >= 9216) return;
    int y = p / 96, x = p % 96;
    const float* zr = z   + ((long)n * 59 + o) * 9216;
    const float* an = att + (long)n * 82944;
    float acc = bias[o];
    #pragma unroll
    for (int k = 0; k < 9; k++) {
        int yy = y + (k / 3 - 1) * 2;
        int xx = x + (k % 3 - 1) * 2;
        float zv = ((unsigned)yy < 96u && (unsigned)xx < 96u) ? zr[yy * 96 + xx] : 0.f;
        acc = fmaf(an[k * 9216 + p], zv, acc);
    }
    out[((long)n * 59 + o) * 9216 + p] = acc;
}

// ---------------------------------------------------------------------------
extern "C" void kernel_launch(void* const* d_in, const int* in_sizes, int n_in,
                              void* d_out, int out_size)
{
    (void)in_sizes; (void)n_in; (void)out_size;
    const float* c1    = (const float*)d_in[0];
    const float* c2    = (const float*)d_in[1];
    const float* x     = (const float*)d_in[2];
    const float* w_r1  = (const float*)d_in[3];
    const float* bnr1  = (const float*)d_in[4];
    const float* w_r2  = (const float*)d_in[5];
    const float* bnr2  = (const float*)d_in[6];
    const float* w_r3  = (const float*)d_in[7];
    const float* bnr3  = (const float*)d_in[8];
    const float* w_c5  = (const float*)d_in[17];
    const float* bnc5  = (const float*)d_in[18];
    const float* w_c6  = (const float*)d_in[19];
    const float* b_c6  = (const float*)d_in[20];

    float *r1p, *r2p, *t48p, *c2rp, *attp, *poolp, *ppolp, *o5p, *z48p, *z96p;
    __half *psphp, *w5hp;
    cudaGetSymbolAddress((void**)&r1p,  g_r1b);
    cudaGetSymbolAddress((void**)&r2p,  g_r2b);
    cudaGetSymbolAddress((void**)&t48p, g_t48);
    cudaGetSymbolAddress((void**)&c2rp, g_c2r);
    cudaGetSymbolAddress((void**)&attp, g_attb);
    cudaGetSymbolAddress((void**)&poolp, g_pool);
    cudaGetSymbolAddress((void**)&ppolp, g_ppol);
    cudaGetSymbolAddress((void**)&psphp, g_psph);
    cudaGetSymbolAddress((void**)&o5p,  g_out5);
    cudaGetSymbolAddress((void**)&z48p, g_z48);
    cudaGetSymbolAddress((void**)&z96p, g_z96);
    cudaGetSymbolAddress((void**)&w5hp, g_w5h);

    const int c5_smem = 2 * HBUF * sizeof(__half);  // 73728 B
    cudaFuncSetAttribute(c5_mma_kernel, cudaFuncAttributeMaxDynamicSharedMemorySize, c5_smem);

    // Side stream for the attention branch; it fully joins BEFORE c5 launches
    // so nothing ever co-schedules with c5's full-chip wave. Objects created
    // fresh per call (deterministic) and intentionally leaked (no device mem).
    cudaStream_t sA;
    cudaEvent_t  eRoot, eA;
    cudaStreamCreateWithFlags(&sA, cudaStreamNonBlocking);
    cudaEventCreateWithFlags(&eRoot, cudaEventDisableTiming);
    cudaEventCreateWithFlags(&eA,    cudaEventDisableTiming);

    cudaEventRecord(eRoot, 0);
    cudaStreamWaitEvent(sA, eRoot, 0);

    // ---- side stream: query + key + attention (~230 us) ----
    gemm_conv64<2><<<dim3(72, 1, 2), 256, 0, sA>>>(
        w_r1, c1, bnr1, r1p, 2304, 96, 96, 256L * 9216);
    gemm_conv64<2><<<dim3(72, 1, 2), 256, 0, sA>>>(
        w_r2, r1p, bnr2, r2p, 576, 96, 96, 64L * 9216);
    gemm_conv<64, 0, true, false, false, false><<<dim3(18, 1, 2), 128, 0, sA>>>(
        w_r3, c2, bnr3, t48p, 64, 512, 48, 48, 2304, 512L * 2304, 64L * 2304);
    ups48to96<true><<<4608, 256, 0, sA>>>(t48p, c2rp, 2 * 64 * 9216);
    att_kernel<<<dim3(36, 2), 256, 0, sA>>>(r2p, c2rp, attp);
    cudaEventRecord(eA, sA);

    // ---- main stream: weight prep + psp chain (~125 us, overlaps side) ----
    w2h_perm<<<73728, 256>>>(w_c5, w5hp);
    pool_kernel<<<dim3(2048, 2), 64>>>(x, poolp);
    PoolWArgs pa;
    pa.w[0] = (const float*)d_in[9];  pa.bn[0] = (const float*)d_in[10];
    pa.w[1] = (const float*)d_in[11]; pa.bn[1] = (const float*)d_in[12];
    pa.w[2] = (const float*)d_in[13]; pa.bn[2] = (const float*)d_in[14];
    pa.w[3] = (const float*)d_in[15]; pa.bn[3] = (const float*)d_in[16];
    pooled_conv_kernel<<<6400, 256>>>(pa, poolp, ppolp);
    psp_assemble4<<<18432, 256>>>(x, ppolp, psphp);

    // join BEFORE c5: side stream fully drained, c5 gets the whole chip
    cudaStreamWaitEvent(0, eA, 0);

    // ---- c5 -> conv6 -> upsample -> final (all on main stream) ----
    c5_mma_kernel<<<dim3(18, 4, 2), 512, c5_smem>>>(w5hp, psphp, bnc5, o5p);
    gemm_conv<64, 0, false, false, true, false><<<dim3(18, 1, 2), 128>>>(
        w_c6, o5p, nullptr, z48p, 59, 512, 48, 48, 2304, 512L * 2304, 59L * 2304);
    ups48to96<false><<<4248, 256>>>(z48p, z96p, 2 * 59 * 9216);
    final_kernel<<<dim3(36, 59, 2), 256>>>(attp, z96p, b_c6, (float*)d_out);
}

// round 17
// speedup vs baseline: 1.2171x; 1.2171x over previous
#include <cuda_runtime.h>
#include <cuda_fp16.h>
#include <cstdint>

// ---------------- scratch (device globals; no allocation allowed) ----------
__device__ float  g_r1b [1179648];  // [2][64][96][96]
__device__ float  g_r2b [1179648];  // [2][64][96][96]  query q
__device__ float  g_t48 [294912];   // [2][64][48][48]
__device__ float  g_c2r [1179648];  // [2][64][96][96]  keys
__device__ float  g_attb[165888];   // [2][9][9216]
__device__ float  g_pool[204800];
__device__ float  g_ppol[51200];
__device__ __half g_psph[18874368]; // [2][4096][48][48] psp features (half)
__device__ float  g_out5[2359296];  // [2][512][48][48]
__device__ float  g_z48 [271872];
__device__ float  g_z96 [1087488];
__device__ __half g_w5h [18874368]; // w_c5 as half, PERMUTED [512][tap*4096+cin]

__device__ __forceinline__ uint32_t smem_u32(const void* p) {
    uint32_t a;
    asm("{ .reg .u64 t; cvta.to.shared.u64 t, %1; cvt.u32.u64 %0, t; }" : "=r"(a) : "l"(p));
    return a;
}
__device__ __forceinline__ void ldsm_x4(uint32_t& r0, uint32_t& r1, uint32_t& r2,
                                        uint32_t& r3, uint32_t addr) {
    asm volatile("ldmatrix.sync.aligned.m8n8.x4.shared.b16 {%0,%1,%2,%3}, [%4];"
                 : "=r"(r0), "=r"(r1), "=r"(r2), "=r"(r3) : "r"(addr));
}
__device__ __forceinline__ void mma16n8k16(float* c, const uint32_t* a, const uint32_t* b)
{
    asm volatile(
        "mma.sync.aligned.m16n8k16.row.col.f32.f16.f16.f32 "
        "{%0,%1,%2,%3}, {%4,%5,%6,%7}, {%8,%9}, {%0,%1,%2,%3};"
        : "+f"(c[0]), "+f"(c[1]), "+f"(c[2]), "+f"(c[3])
        : "r"(a[0]), "r"(a[1]), "r"(a[2]), "r"(a[3]), "r"(b[0]), "r"(b[1]));
}

// -------- convert + permute w_c5 (tiled, coalesced both ways) --------------
// dst[m][tap*4096 + cin] = src[m][cin*9 + tap]
// block = (cin-tile of 256, m); reads 2304 contiguous floats, writes 9 runs
// of 256 contiguous halves. SMEM read stride 9 (coprime 32) conflict-free.
__global__ void w2h_perm(const float* __restrict__ src, __half* __restrict__ dst)
{
    __shared__ float tl[2304];
    const int m    = blockIdx.y;
    const int cin0 = blockIdx.x * 256;
    const float* s = src + (long)m * 36864 + (long)cin0 * 9;
    for (int i = threadIdx.x; i < 2304; i += 256) tl[i] = s[i];
    __syncthreads();
    __half* d = dst + (long)m * 36864 + cin0;
    for (int i = threadIdx.x; i < 2304; i += 256) {
        int tap = i >> 8;          // 0..8
        int c   = i & 255;
        d[tap * 4096 + c] = __float2half(tl[c * 9 + tap]);
    }
}

// ===========================================================================
// conv5: fp16 mma.sync (f32 accum) + ldmatrix, TAP-MAJOR implicit im2col.
//   k' = tap*4096 + cin; each KC=128 chunk has a single tap.
//   CTA 128x128, 16 warps (warp 32x32), double-buffered dynamic smem (139KB).
//   A smem [m][136h], B smem [n][136h]; stride 136h -> conflict-free LDSM.
// ===========================================================================
#define KC5  128
#define SAK  136
#define HBUF (2 * 128 * SAK)   // halves per (A|B) pair = 34816

__global__ void __launch_bounds__(512, 1)
c5_mma_kernel(const __half* __restrict__ Ah, const __half* __restrict__ psph,
              const float* __restrict__ bnp, float* __restrict__ Out)
{
    extern __shared__ __half smh[];
    const uint32_t smbase = smem_u32(smh);

    const int t    = threadIdx.x;
    const int wid  = t >> 5;
    const int lane = t & 31;
    const int gid  = lane >> 2;
    const int tig  = lane & 3;
    const int wm   = (wid & 3) * 32;
    const int wn   = (wid >> 2) * 32;

    const int img = blockIdx.z;
    const int bm  = blockIdx.y * 128;
    const int bp0 = blockIdx.x * 128;
    const __half* Bn = psph + (long)img * 4096 * 2304;

    const int rowA = lane & 15;
    const int colA = (lane & 16) ? 8 : 0;
    const int rowB = (lane & 7) + ((lane & 16) ? 8 : 0);
    const int colB = (lane & 8) ? 8 : 0;

    // A loader: 4 units of 16B; unit u = j*512+t -> row = u>>4, seg = u&15
    const int a_row = t >> 4;          // 0..31 (+32 per j)
    const int a_seg = t & 15;

    // B loader: 4 units; unit u = j*512+t -> n = u&127, kg = u>>7 (0..15)
    const int b_n  = t & 127;
    const int b_kg0 = t >> 7;          // 0..3 (+4 per j)
    const int pg   = bp0 + b_n;
    const int b_py = pg / 48;
    const int b_px = pg - b_py * 48;

    uint4 arv[4];
    __align__(16) uint16_t brv[4][8];

    auto fetchA = [&](int k0) {
        #pragma unroll
        for (int j = 0; j < 4; j++)
            arv[j] = *reinterpret_cast<const uint4*>(
                Ah + (long)(bm + a_row + j * 32) * 36864 + k0 + a_seg * 8);
    };
    // chunk ch: tap = ch>>5 (one tap per chunk), cin0 = (ch&31)*128
    auto fetchB = [&](int ch) {
        const int tap  = ch >> 5;
        const int cin0 = (ch & 31) << 7;
        const int dy   = tap / 3 - 1;
        const int dx   = tap - (tap / 3) * 3 - 1;
        const int y    = b_py + dy;
        const int x    = b_px + dx;
        const bool valid = ((unsigned)y < 48u) && ((unsigned)x < 48u);
        #pragma unroll
        for (int j = 0; j < 4; j++) {
            const __half* bp = Bn + (long)(cin0 + (b_kg0 + j * 4) * 8) * 2304
                                  + y * 48 + x;
            #pragma unroll
            for (int q = 0; q < 8; q++)
                brv[j][q] = valid ? __half_as_ushort(__ldg(bp + q * 2304))
                                  : (uint16_t)0;
        }
    };
    auto stsAB = [&](int buf) {
        __half* A = smh + buf * HBUF;
        __half* B = A + 128 * SAK;
        #pragma unroll
        for (int j = 0; j < 4; j++)
            *reinterpret_cast<uint4*>(A + (a_row + j * 32) * SAK + a_seg * 8) = arv[j];
        #pragma unroll
        for (int j = 0; j < 4; j++)
            *reinterpret_cast<uint4*>(B + b_n * SAK + (b_kg0 + j * 4) * 8) =
                *reinterpret_cast<const uint4*>(brv[j]);
    };

    float acc[2][4][4];
    #pragma unroll
    for (int mt = 0; mt < 2; mt++)
        #pragma unroll
        for (int nt = 0; nt < 4; nt++)
            #pragma unroll
            for (int i = 0; i < 4; i++) acc[mt][nt][i] = 0.f;

    fetchA(0); fetchB(0);
    stsAB(0);
    __syncthreads();

    const int NCH = 288;  // 36864 / 128
    int buf = 0;
    for (int it = 0; it < NCH; it++) {
        if (it + 1 < NCH) { fetchA((it + 1) * KC5); fetchB(it + 1); }
        const uint32_t Abase = smbase + (uint32_t)buf * (HBUF * 2);
        const uint32_t Bbase = Abase + 128 * SAK * 2;
        #pragma unroll
        for (int s = 0; s < 8; s++) {
            uint32_t af[2][4];
            uint32_t bf[4][2];
            #pragma unroll
            for (int mt = 0; mt < 2; mt++)
                ldsm_x4(af[mt][0], af[mt][1], af[mt][2], af[mt][3],
                        Abase + (uint32_t)((wm + mt * 16 + rowA) * SAK
                                           + s * 16 + colA) * 2u);
            #pragma unroll
            for (int np = 0; np < 2; np++)
                ldsm_x4(bf[2 * np][0], bf[2 * np][1], bf[2 * np + 1][0], bf[2 * np + 1][1],
                        Bbase + (uint32_t)((wn + np * 16 + rowB) * SAK
                                           + s * 16 + colB) * 2u);
            #pragma unroll
            for (int mt = 0; mt < 2; mt++)
                #pragma unroll
                for (int nt = 0; nt < 4; nt++)
                    mma16n8k16(acc[mt][nt], af[mt], bf[nt]);
        }
        if (it + 1 < NCH) stsAB(buf ^ 1);
        __syncthreads();
        buf ^= 1;
    }

    #pragma unroll
    for (int mt = 0; mt < 2; mt++) {
        const int m0 = bm + wm + mt * 16 + gid;
        #pragma unroll
        for (int half = 0; half < 2; half++) {
            const int m = m0 + half * 8;
            const float g  = bnp[m], be = bnp[512 + m];
            const float mu = bnp[1024 + m], va = bnp[1536 + m];
            const float scale = g * rsqrtf(va + 1e-5f);
            const float shift = be - mu * scale;
            float* On = Out + ((long)img * 512 + m) * 2304 + bp0 + wn + tig * 2;
            #pragma unroll
            for (int nt = 0; nt < 4; nt++) {
                float2 v;
                v.x = fmaxf(fmaf(acc[mt][nt][half * 2],     scale, shift), 0.f);
                v.y = fmaxf(fmaf(acc[mt][nt][half * 2 + 1], scale, shift), 0.f);
                *reinterpret_cast<float2*>(On + nt * 8) = v;
            }
        }
    }
}

// ========== fp32 SGEMM, 256 threads, tile 64x128 (dilated 3x3, M=64) =======
template<int DIL>
__global__ void __launch_bounds__(256, 1)
gemm_conv64(const float* __restrict__ A, const float* __restrict__ Bin,
            const float* __restrict__ bnp, float* __restrict__ Out,
            int K, int H, int W, long inStride)
{
    __shared__ float As_[2][8][64];
    __shared__ float Bs_[2][8][128];

    const int t   = threadIdx.x;
    const int img = blockIdx.z;
    const int Npix = H * W;
    const float* Bn = Bin + (long)img * inStride;
    float*       On = Out + (long)img * 64L * Npix;
    const int bp0 = blockIdx.x * 128;
    const int tr  = t >> 4;
    const int tc  = t & 15;

    const int am  = t >> 2;
    const int ak2 = (t & 3) * 2;
    const int bk  = t >> 5;
    const int bp4 = (t & 31) * 4;

    float2 aReg;
    float  bReg[4];

    auto fetch = [&](int k0) {
        aReg = *reinterpret_cast<const float2*>(A + (long)am * K + k0 + ak2);
        int k   = k0 + bk;
        int cin = k / 9;
        int tap = k - cin * 9;
        int oy  = (tap / 3 - 1) * DIL;
        int ox  = (tap % 3 - 1) * DIL;
        const float* src = Bn + (long)cin * Npix;
        #pragma unroll
        for (int j = 0; j < 4; j++) {
            int p  = bp0 + bp4 + j;
            int py = p / W;
            int px = p - py * W;
            int y  = py + oy;
            int x  = px + ox;
            bReg[j] = ((unsigned)y < (unsigned)H && (unsigned)x < (unsigned)W)
                      ? src[y * W + x] : 0.f;
        }
    };
    auto put = [&](int buf) {
        As_[buf][ak2 + 0][am] = aReg.x;
        As_[buf][ak2 + 1][am] = aReg.y;
        #pragma unroll
        for (int j = 0; j < 4; j++) Bs_[buf][bk][bp4 + j] = bReg[j];
    };

    float acc[4][8];
    #pragma unroll
    for (int i = 0; i < 4; i++)
        #pragma unroll
        for (int j = 0; j < 8; j++) acc[i][j] = 0.f;

    fetch(0);
    put(0);
    __syncthreads();

    const int nK = K / 8;
    int buf = 0;
    for (int it = 0; it < nK; it++) {
        if (it + 1 < nK) fetch((it + 1) * 8);
        #pragma unroll
        for (int kk = 0; kk < 8; kk++) {
            float4 a0 = *reinterpret_cast<const float4*>(&As_[buf][kk][tr * 4]);
            float4 b0 = *reinterpret_cast<const float4*>(&Bs_[buf][kk][tc * 8]);
            float4 b1 = *reinterpret_cast<const float4*>(&Bs_[buf][kk][tc * 8 + 4]);
            float av[4] = {a0.x, a0.y, a0.z, a0.w};
            float bv[8] = {b0.x, b0.y, b0.z, b0.w, b1.x, b1.y, b1.z, b1.w};
            #pragma unroll
            for (int i = 0; i < 4; i++)
                #pragma unroll
                for (int j = 0; j < 8; j++)
                    acc[i][j] = fmaf(av[i], bv[j], acc[i][j]);
        }
        if (it + 1 < nK) put(buf ^ 1);
        __syncthreads();
        buf ^= 1;
    }

    #pragma unroll
    for (int i = 0; i < 4; i++) {
        int m = tr * 4 + i;
        float g  = bnp[m];
        float be = bnp[64 + m];
        float mu = bnp[128 + m];
        float va = bnp[192 + m];
        float scale = g * rsqrtf(va + 1e-5f);
        float shift = be - mu * scale;
        #pragma unroll
        for (int j = 0; j < 8; j++) {
            int p = bp0 + tc * 8 + j;
            float v = fmaxf(fmaf(acc[i][j], scale, shift), 0.f);
            On[(long)m * Npix + p] = v;
        }
    }
}

// ================= fp32 SGEMM (1x1 convs) ==================================
template<int TM, int DIL, bool BN, bool RELU, bool MCHECK, bool NCHECK>
__global__ void __launch_bounds__((TM/8)*16, 1)
gemm_conv(const float* __restrict__ A, const float* __restrict__ Bin,
          const float* __restrict__ bnp, float* __restrict__ Out,
          int M, int K, int H, int W, int Npix,
          long inStride, long outStride)
{
    constexpr int TN   = 128;
    constexpr int NT   = (TM / 8) * (TN / 8);
    constexpr int BVEC = (NT == 256) ? 4 : 8;

    __shared__ float As_[2][8][TM];
    __shared__ float Bs_[2][8][TN];

    const int tid = threadIdx.x;
    const int img = blockIdx.z;
    const float* Bn = Bin + (long)img * inStride;
    float*       On = Out + (long)img * outStride;
    const int bm  = blockIdx.y * TM;
    const int bp0 = blockIdx.x * TN;
    const int tr  = tid / 16;
    const int tc  = tid % 16;

    const int am = tid >> 1;
    const int ak = (tid & 1) * 4;
    const int bk = tid / (TN / BVEC);
    const int bp = (tid % (TN / BVEC)) * BVEC;

    float4 aReg;
    float  bReg[BVEC];

    auto fetch = [&](int k0) {
        int m = bm + am;
        if (!MCHECK || m < M)
            aReg = *reinterpret_cast<const float4*>(A + (long)m * K + k0 + ak);
        else
            aReg = make_float4(0.f, 0.f, 0.f, 0.f);
        int k = k0 + bk;
        if (DIL == 0) {
            const float* row = Bn + (long)k * Npix;
            if (!NCHECK) {
                #pragma unroll
                for (int j = 0; j < BVEC; j += 4) {
                    float4 v = *reinterpret_cast<const float4*>(row + bp0 + bp + j);
                    bReg[j] = v.x; bReg[j+1] = v.y; bReg[j+2] = v.z; bReg[j+3] = v.w;
                }
            } else {
                #pragma unroll
                for (int j = 0; j < BVEC; j++) {
                    int p = bp0 + bp + j;
                    bReg[j] = (p < Npix) ? row[p] : 0.f;
                }
            }
        } else {
            int cin = k / 9;
            int tap = k - cin * 9;
            int oy  = (tap / 3 - 1) * DIL;
            int ox  = (tap % 3 - 1) * DIL;
            const float* src = Bn + (long)cin * (H * W);
            #pragma unroll
            for (int j = 0; j < BVEC; j++) {
                int p  = bp0 + bp + j;
                int py = p / W;
                int px = p - py * W;
                int y  = py + oy;
                int x  = px + ox;
                bReg[j] = ((unsigned)y < (unsigned)H && (unsigned)x < (unsigned)W)
                          ? src[y * W + x] : 0.f;
            }
        }
    };
    auto put = [&](int buf) {
        As_[buf][ak + 0][am] = aReg.x;
        As_[buf][ak + 1][am] = aReg.y;
        As_[buf][ak + 2][am] = aReg.z;
        As_[buf][ak + 3][am] = aReg.w;
        #pragma unroll
        for (int j = 0; j < BVEC; j++) Bs_[buf][bk][bp + j] = bReg[j];
    };

    float acc[8][8];
    #pragma unroll
    for (int i = 0; i < 8; i++)
        #pragma unroll
        for (int j = 0; j < 8; j++) acc[i][j] = 0.f;

    fetch(0);
    put(0);
    __syncthreads();

    const int nK = K / 8;
    int buf = 0;
    for (int it = 0; it < nK; it++) {
        if (it + 1 < nK) fetch((it + 1) * 8);
        #pragma unroll
        for (int kk = 0; kk < 8; kk++) {
            float4 a0 = *reinterpret_cast<const float4*>(&As_[buf][kk][tr * 8]);
            float4 a1 = *reinterpret_cast<const float4*>(&As_[buf][kk][tr * 8 + 4]);
            float4 b0 = *reinterpret_cast<const float4*>(&Bs_[buf][kk][tc * 8]);
            float4 b1 = *reinterpret_cast<const float4*>(&Bs_[buf][kk][tc * 8 + 4]);
            float av[8] = {a0.x, a0.y, a0.z, a0.w, a1.x, a1.y, a1.z, a1.w};
            float bv[8] = {b0.x, b0.y, b0.z, b0.w, b1.x, b1.y, b1.z, b1.w};
            #pragma unroll
            for (int i = 0; i < 8; i++)
                #pragma unroll
                for (int j = 0; j < 8; j++)
                    acc[i][j] = fmaf(av[i], bv[j], acc[i][j]);
        }
        if (it + 1 < nK) put(buf ^ 1);
        __syncthreads();
        buf ^= 1;
    }

    #pragma unroll
    for (int i = 0; i < 8; i++) {
        int m = bm + tr * 8 + i;
        if (MCHECK && m >= M) continue;
        float scale = 1.f, shift = 0.f;
        if (BN) {
            float g  = bnp[m];
            float be = bnp[M + m];
            float mu = bnp[2 * M + m];
            float va = bnp[3 * M + m];
            scale = g * rsqrtf(va + 1e-5f);
            shift = be - mu * scale;
        }
        #pragma unroll
        for (int j = 0; j < 8; j++) {
            int p = bp0 + tc * 8 + j;
            if (NCHECK && p >= Npix) continue;
            float v = acc[i][j];
            if (BN)   v = fmaf(v, scale, shift);
            if (RELU) v = fmaxf(v, 0.f);
            On[(long)m * Npix + p] = v;
        }
    }
}

// -------- adaptive avg pool ------------------------------------------------
__global__ void pool_kernel(const float* __restrict__ x, float* __restrict__ pool)
{
    __shared__ float sm[2304];
    const int cin = blockIdx.x;
    const int n   = blockIdx.y;
    const float* src = x + ((long)n * 2048 + cin) * 2304;
    for (int i = threadIdx.x; i < 2304; i += blockDim.x) sm[i] = src[i];
    __syncthreads();
    int r = threadIdx.x;
    if (r < 50) {
        int sc, pi;
        if      (r < 1)  { sc = 0; pi = r; }
        else if (r < 5)  { sc = 1; pi = r - 1; }
        else if (r < 14) { sc = 2; pi = r - 5; }
        else             { sc = 3; pi = r - 14; }
        const int sides[4] = {1, 2, 3, 6};
        const int inoff[4] = {0, 2048, 10240, 28672};
        int side = sides[sc];
        int iy = pi / side, ix = pi % side;
        int bs = 48 / side;
        float s = 0.f;
        for (int yy = iy * bs; yy < (iy + 1) * bs; yy++)
            for (int xx = ix * bs; xx < (ix + 1) * bs; xx++)
                s += sm[yy * 48 + xx];
        pool[(long)n * 102400 + inoff[sc] + cin * (side * side) + pi] = s / (float)(bs * bs);
    }
}

struct PoolWArgs { const float* w[4]; const float* bn[4]; };

__global__ void pooled_conv_kernel(PoolWArgs args, const float* __restrict__ pool,
                                   float* __restrict__ ppool)
{
    int gw   = (blockIdx.x * blockDim.x + threadIdx.x) >> 5;
    int lane = threadIdx.x & 31;
    if (gw >= 51200) return;
    int n  = gw / 25600;
    int t  = gw % 25600;
    int pg = t / 512;
    int co = t % 512;
    int sc, pi;
    if      (pg < 1)  { sc = 0; pi = pg; }
    else if (pg < 5)  { sc = 1; pi = pg - 1; }
    else if (pg < 14) { sc = 2; pi = pg - 5; }
    else              { sc = 3; pi = pg - 14; }
    const int ssq[4]    = {1, 4, 9, 36};
    const int inoff[4]  = {0, 2048, 10240, 28672};
    const int outoff[4] = {0, 512, 2560, 7168};
    const float* w  = args.w[sc] + (long)co * 2048;
    const float* pb = pool + (long)n * 102400 + inoff[sc] + pi;
    int stride = ssq[sc];
    float acc = 0.f;
    for (int c = lane; c < 2048; c += 32)
        acc = fmaf(w[c], pb[(long)c * stride], acc);
    #pragma unroll
    for (int s = 16; s; s >>= 1) acc += __shfl_xor_sync(0xffffffffu, acc, s);
    if (lane == 0) {
        const float* bnp = args.bn[sc];
        float scale = bnp[co] * rsqrtf(bnp[1536 + co] + 1e-5f);
        float v = fmaf(acc, scale, bnp[512 + co] - bnp[1024 + co] * scale);
        ppool[(long)n * 25600 + outoff[sc] + co * stride + pi] = fmaxf(v, 0.f);
    }
}

// -------- assemble psp (HALF out, 4 px per thread) -------------------------
__global__ void psp_assemble4(const float* __restrict__ x, const float* __restrict__ ppool,
                              __half* __restrict__ psp)
{
    long q = (long)blockIdx.x * 256 + threadIdx.x;
    if (q >= 4718592L) return;          // 18874368 / 4
    long idx = q * 4;
    int p = (int)(idx % 2304);          // multiple of 4, same (n,c) for all 4
    long tt = idx / 2304;
    int c = (int)(tt % 4096);
    int n = (int)(tt / 4096);
    __half h[4];
    if (c < 2048) {
        float4 v = *reinterpret_cast<const float4*>(
            x + ((long)n * 2048 + c) * 2304 + p);
        h[0] = __float2half(v.x); h[1] = __float2half(v.y);
        h[2] = __float2half(v.z); h[3] = __float2half(v.w);
    } else {
        int sc = (c - 2048) >> 9;
        int cc = (c - 2048) & 511;
        const int sides[4]  = {1, 2, 3, 6};
        const int outoff[4] = {0, 512, 2560, 7168};
        int s = sides[sc];
        const float* f = ppool + (long)n * 25600 + outoff[sc] + cc * s * s;
        if (s == 1) {
            h[0] = h[1] = h[2] = h[3] = __float2half(f[0]);
        } else {
            int y = p / 48;
            float ratio = (float)(s - 1) / 47.0f;
            float sy = y * ratio;
            int y0 = (int)sy;
            if (y0 > s - 1) y0 = s - 1;
            int y1 = min(y0 + 1, s - 1);
            float wy = sy - y0;
            #pragma unroll
            for (int j = 0; j < 4; j++) {
                int xx = (p + j) % 48;
                float sx = xx * ratio;
                int x0 = (int)sx;
                if (x0 > s - 1) x0 = s - 1;
                int x1 = min(x0 + 1, s - 1);
                float wx = sx - x0;
                float r0 = f[y0 * s + x0] * (1.f - wx) + f[y0 * s + x1] * wx;
                float r1 = f[y1 * s + x0] * (1.f - wx) + f[y1 * s + x1] * wx;
                h[j] = __float2half(r0 * (1.f - wy) + r1 * wy);
            }
        }
    }
    uint2 packed;
    packed.x = ((uint32_t)__half_as_ushort(h[1]) << 16) | __half_as_ushort(h[0]);
    packed.y = ((uint32_t)__half_as_ushort(h[3]) << 16) | __half_as_ushort(h[2]);
    *reinterpret_cast<uint2*>(psp + idx) = packed;
}

template<bool RELU>
__global__ void ups48to96(const float* __restrict__ in, float* __restrict__ out, int total)
{
    int idx = blockIdx.x * 256 + threadIdx.x;
    if (idx >= total) return;
    int p  = idx % 9216;
    int ch = idx / 9216;
    int y = p / 96, x = p % 96;
    const float r = 47.0f / 95.0f;
    float sy = y * r, sx = x * r;
    int y0 = (int)sy, x0 = (int)sx;
    if (y0 > 47) y0 = 47;
    if (x0 > 47) x0 = 47;
    int y1 = min(y0 + 1, 47), x1 = min(x0 + 1, 47);
    float wy = sy - y0, wx = sx - x0;
    const float* f = in + (long)ch * 2304;
    float v0 = f[y0 * 48 + x0] * (1.f - wx) + f[y0 * 48 + x1] * wx;
    float v1 = f[y1 * 48 + x0] * (1.f - wx) + f[y1 * 48 + x1] * wx;
    float v  = v0 * (1.f - wy) + v1 * wy;
    if (RELU) v = fmaxf(v, 0.f);
    out[idx] = v;
}

__global__ void att_kernel(const float* __restrict__ q, const float* __restrict__ kf,
                           float* __restrict__ att)
{
    int p = blockIdx.x * 256 + threadIdx.x;
    int n = blockIdx.y;
    if (p >= 9216) return;
    int y = p / 96, x = p % 96;
    int   offs[9];
    bool  valid[9];
    #pragma unroll
    for (int k = 0; k < 9; k++) {
        int yy = y + (k / 3 - 1) * 2;
        int xx = x + (k % 3 - 1) * 2;
        valid[k] = ((unsigned)yy < 96u) && ((unsigned)xx < 96u);
        offs[k]  = valid[k] ? yy * 96 + xx : 0;
    }
    float e[9];
    #pragma unroll
    for (int k = 0; k < 9; k++) e[k] = 0.f;
    const float* qn = q  + (long)n * 64 * 9216;
    const float* kn = kf + (long)n * 64 * 9216;
    for (int c = 0; c < 64; c++) {
        float qv = qn[c * 9216 + p];
        const float* base = kn + c * 9216;
        #pragma unroll
        for (int k = 0; k < 9; k++) {
            float kv = valid[k] ? base[offs[k]] : 0.f;
            e[k] = fmaf(qv, kv, e[k]);
        }
    }
    float mx = e[0];
    #pragma unroll
    for (int k = 1; k < 9; k++) mx = fmaxf(mx, e[k]);
    float sum = 0.f;
    #pragma unroll
    for (int k = 0; k < 9; k++) { e[k] = __expf(e[k] - mx); sum += e[k]; }
    float inv = 1.f / sum;
    #pragma unroll
    for (int k = 0; k < 9; k++)
        att[(long)n * 82944 + k * 9216 + p] = e[k] * inv;
}

__global__ void final_kernel(const float* __restrict__ att, const float* __restrict__ z,
                             const float* __restrict__ bias, float* __restrict__ out)
{
    int p = blockIdx.x * 256 + threadIdx.x;
    int o = blockIdx.y;
    int n = blockIdx.z;
    if (p >= 9216) return;
    int y = p / 96, x = p % 96;
    const float* zr = z   + ((long)n * 59 + o) * 9216;
    const float* an = att + (long)n * 82944;
    float acc = bias[o];
    #pragma unroll
    for (int k = 0; k < 9; k++) {
        int yy = y + (k / 3 - 1) * 2;
        int xx = x + (k % 3 - 1) * 2;
        float zv = ((unsigned)yy < 96u && (unsigned)xx < 96u) ? zr[yy * 96 + xx] : 0.f;
        acc = fmaf(an[k * 9216 + p], zv, acc);
    }
    out[((long)n * 59 + o) * 9216 + p] = acc;
}

// ---------------------------------------------------------------------------
extern "C" void kernel_launch(void* const* d_in, const int* in_sizes, int n_in,
                              void* d_out, int out_size)
{
    (void)in_sizes; (void)n_in; (void)out_size;
    const float* c1    = (const float*)d_in[0];
    const float* c2    = (const float*)d_in[1];
    const float* x     = (const float*)d_in[2];
    const float* w_r1  = (const float*)d_in[3];
    const float* bnr1  = (const float*)d_in[4];
    const float* w_r2  = (const float*)d_in[5];
    const float* bnr2  = (const float*)d_in[6];
    const float* w_r3  = (const float*)d_in[7];
    const float* bnr3  = (const float*)d_in[8];
    const float* w_c5  = (const float*)d_in[17];
    const float* bnc5  = (const float*)d_in[18];
    const float* w_c6  = (const float*)d_in[19];
    const float* b_c6  = (const float*)d_in[20];

    float *r1p, *r2p, *t48p, *c2rp, *attp, *poolp, *ppolp, *o5p, *z48p, *z96p;
    __half *psphp, *w5hp;
    cudaGetSymbolAddress((void**)&r1p,  g_r1b);
    cudaGetSymbolAddress((void**)&r2p,  g_r2b);
    cudaGetSymbolAddress((void**)&t48p, g_t48);
    cudaGetSymbolAddress((void**)&c2rp, g_c2r);
    cudaGetSymbolAddress((void**)&attp, g_attb);
    cudaGetSymbolAddress((void**)&poolp, g_pool);
    cudaGetSymbolAddress((void**)&ppolp, g_ppol);
    cudaGetSymbolAddress((void**)&psphp, g_psph);
    cudaGetSymbolAddress((void**)&o5p,  g_out5);
    cudaGetSymbolAddress((void**)&z48p, g_z48);
    cudaGetSymbolAddress((void**)&z96p, g_z96);
    cudaGetSymbolAddress((void**)&w5hp, g_w5h);

    const int c5_smem = 2 * HBUF * sizeof(__half);  // 139264 B
    cudaFuncSetAttribute(c5_mma_kernel, cudaFuncAttributeMaxDynamicSharedMemorySize, c5_smem);

    // 1: convert + permute c5 weights to half (tap-major K), tiled/coalesced
    w2h_perm<<<dim3(16, 512), 256>>>(w_c5, w5hp);
    // 2..4: pyramid pooling chain -> psp (half)
    pool_kernel<<<dim3(2048, 2), 64>>>(x, poolp);
    PoolWArgs pa;
    pa.w[0] = (const float*)d_in[9];  pa.bn[0] = (const float*)d_in[10];
    pa.w[1] = (const float*)d_in[11]; pa.bn[1] = (const float*)d_in[12];
    pa.w[2] = (const float*)d_in[13]; pa.bn[2] = (const float*)d_in[14];
    pa.w[3] = (const float*)d_in[15]; pa.bn[3] = (const float*)d_in[16];
    pooled_conv_kernel<<<6400, 256>>>(pa, poolp, ppolp);
    psp_assemble4<<<18432, 256>>>(x, ppolp, psphp);
    // 5: query conv1
    gemm_conv64<2><<<dim3(72, 1, 2), 256>>>(w_r1, c1, bnr1, r1p, 2304, 96, 96, 256L * 9216);
    // 6: conv5 on tensor cores (fp16, tap-major, KC=128)
    c5_mma_kernel<<<dim3(18, 4, 2), 512, c5_smem>>>(w5hp, psphp, bnc5, o5p);
    // 7: query conv2
    gemm_conv64<2><<<dim3(72, 1, 2), 256>>>(w_r2, r1p, bnr2, r2p, 576, 96, 96, 64L * 9216);
    // 8..10: key branch + attention
    gemm_conv<64, 0, true, false, false, false><<<dim3(18, 1, 2), 128>>>(
        w_r3, c2, bnr3, t48p, 64, 512, 48, 48, 2304, 512L * 2304, 64L * 2304);
    ups48to96<true><<<4608, 256>>>(t48p, c2rp, 2 * 64 * 9216);
    att_kernel<<<dim3(36, 2), 256>>>(r2p, c2rp, attp);
    // 11..13: conv6 (pre-upsample) + aggregate
    gemm_conv<64, 0, false, false, true, false><<<dim3(18, 1, 2), 128>>>(
        w_c6, o5p, nullptr, z48p, 59, 512, 48, 48, 2304, 512L * 2304, 59L * 2304);
    ups48to96<false><<<4248, 256>>>(z48p, z96p, 2 * 59 * 9216);
    final_kernel<<<dim3(36, 59, 2), 256>>>(attp, z96p, b_c6, (float*)d_out);
}